// round 8
// baseline (speedup 1.0000x reference)
#include <cuda_runtime.h>
#include <cuda_fp16.h>
#include <math.h>
#include <stdint.h>

#define MSLQ 64
#define BSQ  128
#define BB   8192      // MSL*BS
#define ENC  1024
#define HID  512
#define H3   1536      // 3*HID
#define EMBQ 50
#define ATOM 64
#define STEPS 49
#define SOS  1

#define LIMB_SCALE 2048.0f
#define INV_LIMB   (1.0f / 2048.0f)

// ---------------- scratch (device globals: no runtime allocation) ----------
__device__ float g_h0[BB * HID];
__device__ float g_h1[BB * HID];
__device__ float g_G1[BB * H3];
__device__ float g_G2[BB * H3];
__device__ float g_T0[ATOM * H3];
__device__ int   g_p[BB];

// fp16 limb planes (limb1 pre-scaled by 2048)
__device__ __align__(256) unsigned short g_h0p[2][BB * HID];
__device__ __align__(256) unsigned short g_h1p[2][BB * HID];
__device__ __align__(256) unsigned short g_w0p[2][H3 * HID];   // w_hh0 limbs
__device__ __align__(256) unsigned short g_w1p[2][H3 * HID];   // w_ih1 limbs
__device__ __align__(256) unsigned short g_w2p[2][H3 * HID];   // w_hh1 limbs

// ---------------- small helpers -------------------------------------------
__device__ __forceinline__ float sigf(float x) { return 1.0f / (1.0f + expf(-x)); }

__device__ __forceinline__ float gru_elem(float ti, float tz, float tn,
                                          float gr, float gz, float gn, float h) {
    float r = sigf(ti + gr);
    float z = sigf(tz + gz);
    float n = tanhf(tn + r * gn);
    return (1.0f - z) * n + z * h;
}

__device__ __forceinline__ uint32_t smem_u32(const void* p) {
    uint32_t a;
    asm("{ .reg .u64 t; cvta.to.shared.u64 t, %1; cvt.u32.u64 %0, t; }" : "=r"(a) : "l"(p));
    return a;
}

#define SWZ(o) ((o) ^ (((o) >> 3) & 0x70))

__device__ __forceinline__ void cp16(uint32_t dst, const void* src) {
    asm volatile("cp.async.cg.shared.global [%0], [%1], 16;" :: "r"(dst), "l"(src) : "memory");
}

__device__ __forceinline__ void ldsm4(uint32_t* r, uint32_t addr) {
    asm volatile("ldmatrix.sync.aligned.m8n8.x4.shared.b16 {%0,%1,%2,%3}, [%4];"
                 : "=r"(r[0]), "=r"(r[1]), "=r"(r[2]), "=r"(r[3]) : "r"(addr));
}

__device__ __forceinline__ void mma16816h(float* c, const uint32_t* a, const uint32_t* b) {
    asm volatile("mma.sync.aligned.m16n8k16.row.col.f32.f16.f16.f32 "
                 "{%0,%1,%2,%3}, {%4,%5,%6,%7}, {%8,%9}, {%0,%1,%2,%3};"
                 : "+f"(c[0]), "+f"(c[1]), "+f"(c[2]), "+f"(c[3])
                 : "r"(a[0]), "r"(a[1]), "r"(a[2]), "r"(a[3]), "r"(b[0]), "r"(b[1]));
}

// ---------------- fp16 2-limb split (limb1 scaled by 2048) ----------------
__device__ __forceinline__ void split1h(float v, unsigned short& s0, unsigned short& s1) {
    __half t0 = __float2half_rn(v);
    float r = (v - __half2float(t0)) * LIMB_SCALE;
    __half t1 = __float2half_rn(r);
    s0 = __half_as_ushort(t0);
    s1 = __half_as_ushort(t1);
}

__device__ __forceinline__ void split_store4h(float4 o, size_t off,
                                              unsigned short* P0, unsigned short* P1) {
    float v[4] = {o.x, o.y, o.z, o.w};
    unsigned short a0[4], a1[4];
#pragma unroll
    for (int j = 0; j < 4; j++) split1h(v[j], a0[j], a1[j]);
    *(ushort4*)(P0 + off) = make_ushort4(a0[0], a0[1], a0[2], a0[3]);
    *(ushort4*)(P1 + off) = make_ushort4(a1[0], a1[1], a1[2], a1[3]);
}

__global__ void split2_kernel(const float* __restrict__ x,
                              unsigned short* __restrict__ p0,
                              unsigned short* __restrict__ p1, int n) {
    int i = blockIdx.x * blockDim.x + threadIdx.x;
    if (i >= n) return;
    unsigned short s0, s1;
    split1h(x[i], s0, s1);
    p0[i] = s0; p1[i] = s1;
}

// ---------------- init p = SOS --------------------------------------------
__global__ void initp_kernel() {
    int i = blockIdx.x * blockDim.x + threadIdx.x;
    if (i < BB) g_p[i] = SOS;
}

// ---------------- T0[a][n] = b_ih0[n] + sum_k emb[a][k] * w_ih0[n][k] ------
__global__ void table_kernel(const float* __restrict__ emb,
                             const float* __restrict__ w_ih0,
                             const float* __restrict__ b_ih0) {
    int n = blockIdx.x * blockDim.x + threadIdx.x;
    int a = blockIdx.y;
    if (n >= H3) return;
    float acc = b_ih0[n];
    const float* er = emb + a * EMBQ;
    const float* wr = w_ih0 + n * EMBQ;
#pragma unroll
    for (int k = 0; k < EMBQ; k++) acc += er[k] * wr[k];
    g_T0[a * H3 + n] = acc;
}

// ---------------- fp32 SIMT GEMM (init only): tanh + split to h0/h1 -------
#define BMT 128
#define BNT 128
#define BKT 16

__device__ __forceinline__ unsigned long long splat2(float a) {
    unsigned long long d;
    unsigned int u = __float_as_uint(a);
    asm("mov.b64 %0, {%1, %1};" : "=l"(d) : "r"(u));
    return d;
}
__device__ __forceinline__ void fma2(unsigned long long& c, unsigned long long a, unsigned long long b) {
    asm("fma.rn.f32x2 %0, %1, %2, %0;" : "+l"(c) : "l"(a), "l"(b));
}
__device__ __forceinline__ float2 unpack2(unsigned long long c) {
    unsigned int lo, hi;
    asm("mov.b64 {%0, %1}, %2;" : "=r"(lo), "=r"(hi) : "l"(c));
    float2 f; f.x = __uint_as_float(lo); f.y = __uint_as_float(hi);
    return f;
}

__global__ __launch_bounds__(256, 2) void gemm_init_kernel(
    const float* __restrict__ A, const float* __restrict__ W,
    const float* __restrict__ bias, int K)
{
    __shared__ float As[BKT][BMT];
    __shared__ float Ws[BKT][BNT];

    int tid = threadIdx.x;
    int m0 = blockIdx.y * BMT;
    int n0 = blockIdx.x * BNT;
    int tr = tid >> 4;
    int tc = tid & 15;

    unsigned long long acc[8][4];
#pragma unroll
    for (int i = 0; i < 8; i++)
#pragma unroll
        for (int j = 0; j < 4; j++) acc[i][j] = 0ull;

    for (int kt = 0; kt < K; kt += BKT) {
#pragma unroll
        for (int l = 0; l < 2; l++) {
            int fid = tid + l * 256;
            int r = fid >> 2;
            int c4 = (fid & 3) * 4;
            float4 va = *(const float4*)(A + (size_t)(m0 + r) * K + kt + c4);
            As[c4 + 0][r] = va.x; As[c4 + 1][r] = va.y;
            As[c4 + 2][r] = va.z; As[c4 + 3][r] = va.w;
            float4 vw = *(const float4*)(W + (size_t)(n0 + r) * K + kt + c4);
            Ws[c4 + 0][r] = vw.x; Ws[c4 + 1][r] = vw.y;
            Ws[c4 + 2][r] = vw.z; Ws[c4 + 3][r] = vw.w;
        }
        __syncthreads();
#pragma unroll
        for (int k = 0; k < BKT; k++) {
            float4 a0 = *(const float4*)&As[k][tr * 8];
            float4 a1 = *(const float4*)&As[k][tr * 8 + 4];
            float av[8] = {a0.x, a0.y, a0.z, a0.w, a1.x, a1.y, a1.z, a1.w};
            const unsigned long long* wp = (const unsigned long long*)&Ws[k][0];
            unsigned long long bv[4];
#pragma unroll
            for (int j = 0; j < 4; j++) bv[j] = wp[tc * 4 + j];
#pragma unroll
            for (int i = 0; i < 8; i++) {
                unsigned long long as = splat2(av[i]);
#pragma unroll
                for (int j = 0; j < 4; j++) fma2(acc[i][j], as, bv[j]);
            }
        }
        __syncthreads();
    }

    int nb = n0 + tc * 8;
    float bb[8];
#pragma unroll
    for (int j = 0; j < 8; j++) bb[j] = bias[nb + j];

#pragma unroll
    for (int i = 0; i < 8; i++) {
        int m = m0 + tr * 8 + i;
#pragma unroll
        for (int jp = 0; jp < 4; jp++) {
            float2 f = unpack2(acc[i][jp]);
            float v0 = tanhf(f.x + bb[2 * jp]);
            float v1 = tanhf(f.y + bb[2 * jp + 1]);
            int n = nb + 2 * jp;
            if (n < HID) {
                g_h0[m * HID + n] = v0;
                g_h0[m * HID + n + 1] = v1;
            } else {
                g_h1[m * HID + n - HID] = v0;
                g_h1[m * HID + n - HID + 1] = v1;
            }
        }
    }
}

// ---------------- mma.sync fp16x3 GEMM: C = bias + A*W^T (fp32-emulated) ---
// 256 threads, 8 warps in 2x4 grid, warp tile 64x32; CTA tile 128x128.
// 2 fp16 limbs per operand, 3 products: a0b0 -> acc0; a0b1s + a1s b0 -> acc1.
// C = acc0 + acc1/2048 + bias. blockIdx.z selects operand set.
#define KCH 64
#define NCHUNK (HID / KCH)       // 8
#define PART_BYTES (128 * 128)   // 128 rows x 128B (one limb, one chunk)
#define BUF_BYTES (4 * PART_BYTES)   // A0,A1,B0,B1
#define NSTAGE 3
#define NT 256

__global__ __launch_bounds__(NT, 1) void gemm_mma_kernel(
    const unsigned short* __restrict__ Aa, const unsigned short* __restrict__ Wa,
    const float* __restrict__ biasa, float* __restrict__ Ca,
    const unsigned short* __restrict__ Ab, const unsigned short* __restrict__ Wb,
    const float* __restrict__ biasb, float* __restrict__ Cb,
    int hplane, int wplane)
{
    extern __shared__ __align__(1024) char smem[];
    const uint32_t sb = smem_u32(smem);
    const int tid = threadIdx.x;
    const int wid = tid >> 5;
    const int lane = tid & 31;
    const int n0 = blockIdx.x * 128;
    const int m0 = blockIdx.y * 128;

    const unsigned short* A = (blockIdx.z == 0) ? Aa : Ab;
    const unsigned short* W = (blockIdx.z == 0) ? Wa : Wb;
    const float* bias        = (blockIdx.z == 0) ? biasa : biasb;
    float* C                 = (blockIdx.z == 0) ? Ca : Cb;

    const int wm = wid & 1;          // 2 warp-rows (64 m each)
    const int wn = wid >> 1;         // 4 warp-cols (32 n each)
    const int mW = wm * 64;
    const int nW = wn * 32;

    // ldmatrix per-thread address components
    const int a_row = ((lane >> 3) & 1) * 8 + (lane & 7);
    const int a_hb  = (lane >> 4) * 16;          // k-half byte for A
    const int b_row = ((lane >> 4) & 1) * 8 + (lane & 7);
    const int b_hb  = ((lane >> 3) & 1) * 16;    // k-half byte for B

    const char* Ap[2];
    const char* Bp[2];
#pragma unroll
    for (int p = 0; p < 2; p++) {
        Ap[p] = (const char*)(A + (size_t)p * hplane);
        Bp[p] = (const char*)(W + (size_t)p * wplane);
    }

    float c0[4][4][4], c1[4][4][4];
#pragma unroll
    for (int i = 0; i < 4; i++)
#pragma unroll
        for (int j = 0; j < 4; j++)
#pragma unroll
            for (int q = 0; q < 4; q++) { c0[i][j][q] = 0.f; c1[i][j][q] = 0.f; }

    auto load_chunk = [&](int c) {
        int buf = c % NSTAGE;
        uint32_t base = sb + buf * BUF_BYTES;
#pragma unroll
        for (int p = 0; p < 2; p++) {
            const char* srcA = Ap[p] + (size_t)m0 * 1024 + c * 128;   // row stride 512*2B
            uint32_t da = base + p * PART_BYTES;
#pragma unroll
            for (int i = tid; i < 1024; i += NT) {
                int row = i >> 3, seg = (i & 7) << 4;
                cp16(da + SWZ(row * 128 + seg), srcA + (size_t)row * 1024 + seg);
            }
            const char* srcB = Bp[p] + (size_t)n0 * 1024 + c * 128;
            uint32_t db = base + (2 + p) * PART_BYTES;
#pragma unroll
            for (int i = tid; i < 1024; i += NT) {
                int row = i >> 3, seg = (i & 7) << 4;
                cp16(db + SWZ(row * 128 + seg), srcB + (size_t)row * 1024 + seg);
            }
        }
        asm volatile("cp.async.commit_group;" ::: "memory");
    };

    load_chunk(0);
    load_chunk(1);

    for (int c = 0; c < NCHUNK; c++) {
        if (c + 1 < NCHUNK) {
            asm volatile("cp.async.wait_group 1;" ::: "memory");   // chunk c arrived
        } else {
            asm volatile("cp.async.wait_group 0;" ::: "memory");
        }
        __syncthreads();   // all warps finished consuming chunk c-1; chunk c visible
        if (c + 2 < NCHUNK) load_chunk(c + 2);

        uint32_t base = sb + (c % NSTAGE) * BUF_BYTES;

#pragma unroll
        for (int kk = 0; kk < 4; kk++) {
            const int k0b = kk * 32;
            uint32_t a0f[4][4], a1f[4][4], b0f[8], b1f[8];

            auto ldA = [&](int p, uint32_t (*af)[4]) {
                uint32_t pb = base + p * PART_BYTES;
#pragma unroll
                for (int mi = 0; mi < 4; mi++) {
                    int row = mW + mi * 16 + a_row;
                    ldsm4(af[mi], pb + SWZ(row * 128 + k0b + a_hb));
                }
            };
            auto ldB = [&](int p, uint32_t* bf) {
                uint32_t pb = base + (2 + p) * PART_BYTES;
#pragma unroll
                for (int j = 0; j < 2; j++) {
                    int row = nW + j * 16 + b_row;
                    ldsm4(bf + j * 4, pb + SWZ(row * 128 + k0b + b_hb));
                }
            };
            auto mmaset = [&](float (*cc)[4][4], uint32_t (*af)[4], uint32_t* bf) {
#pragma unroll
                for (int mi = 0; mi < 4; mi++)
#pragma unroll
                    for (int ni = 0; ni < 4; ni++)
                        mma16816h(cc[mi][ni], af[mi], bf + ni * 2);
            };

            ldA(0, a0f); ldB(0, b0f);
            mmaset(c0, a0f, b0f);          // a0*b0 -> acc0
            ldB(1, b1f);
            mmaset(c1, a0f, b1f);          // a0*b1s -> acc1
            ldA(1, a1f);
            mmaset(c1, a1f, b0f);          // a1s*b0 -> acc1
        }
    }

    // ---- epilogue: combine limbs + bias, direct stores ----
    const int tr = lane >> 2;
    const int tc2 = (lane & 3) * 2;
#pragma unroll
    for (int mi = 0; mi < 4; mi++) {
        int row = m0 + mW + mi * 16 + tr;
#pragma unroll
        for (int ni = 0; ni < 4; ni++) {
            int col = n0 + nW + ni * 8 + tc2;
            float bx = bias[col], by = bias[col + 1];
            float2 v0;
            v0.x = c0[mi][ni][0] + c1[mi][ni][0] * INV_LIMB + bx;
            v0.y = c0[mi][ni][1] + c1[mi][ni][1] * INV_LIMB + by;
            *(float2*)&C[(size_t)row * H3 + col] = v0;
            float2 v1;
            v1.x = c0[mi][ni][2] + c1[mi][ni][2] * INV_LIMB + bx;
            v1.y = c0[mi][ni][3] + c1[mi][ni][3] * INV_LIMB + by;
            *(float2*)&C[(size_t)(row + 8) * H3 + col] = v1;
        }
    }
}

// ---------------- gate0 (gi from table, gh in G1; emit h0 + limbs) --------
__global__ __launch_bounds__(256) void gate0_kernel() {
    int idx = blockIdx.x * blockDim.x + threadIdx.x;
    int b = idx >> 7;
    int q = (idx & 127) << 2;
    int p = g_p[b];
    const float* T = g_T0 + p * H3;
    float4 Tr = *(const float4*)(T + q);
    float4 Tz = *(const float4*)(T + HID + q);
    float4 Tn = *(const float4*)(T + 2 * HID + q);
    const float* Gb = g_G1 + (size_t)b * H3;
    float4 Gr = *(const float4*)(Gb + q);
    float4 Gz = *(const float4*)(Gb + HID + q);
    float4 Gn = *(const float4*)(Gb + 2 * HID + q);
    float4 h = *(const float4*)(g_h0 + b * HID + q);
    float4 o;
    o.x = gru_elem(Tr.x, Tz.x, Tn.x, Gr.x, Gz.x, Gn.x, h.x);
    o.y = gru_elem(Tr.y, Tz.y, Tn.y, Gr.y, Gz.y, Gn.y, h.y);
    o.z = gru_elem(Tr.z, Tz.z, Tn.z, Gr.z, Gz.z, Gn.z, h.z);
    o.w = gru_elem(Tr.w, Tz.w, Tn.w, Gr.w, Gz.w, Gn.w, h.w);
    size_t off = (size_t)b * HID + q;
    *(float4*)(g_h0 + off) = o;
    split_store4h(o, off, g_h0p[0], g_h0p[1]);
}

// ---------------- fused gate1 + output ------------------------------------
// Block = 8 batch rows, 256 threads. Phase 1: GRU gate for h1 (store to
// global + limbs + smem). Phase 2: logits + log_softmax + argmax feedback.
__global__ __launch_bounds__(256) void gate1out_kernel(const float* __restrict__ w_out,
                                                       const float* __restrict__ b_out,
                                                       float* __restrict__ Y, int s) {
    __shared__ float hs[8][HID];
    int tid = threadIdx.x;
    int wr = tid >> 5;
    int lane = tid & 31;
    int b0 = blockIdx.x * 8;
    int b = b0 + wr;

    // ---- phase 1: gate (each thread: 16 cols of its row) ----
    const float* Gi = g_G1 + (size_t)b * H3;
    const float* Gh = g_G2 + (size_t)b * H3;
    int q0 = lane * 16;
#pragma unroll
    for (int j = 0; j < 4; j++) {
        int q = q0 + j * 4;
        float4 Ir = *(const float4*)(Gi + q);
        float4 Iz = *(const float4*)(Gi + HID + q);
        float4 In = *(const float4*)(Gi + 2 * HID + q);
        float4 Hr = *(const float4*)(Gh + q);
        float4 Hz = *(const float4*)(Gh + HID + q);
        float4 Hn = *(const float4*)(Gh + 2 * HID + q);
        float4 h = *(const float4*)(g_h1 + (size_t)b * HID + q);
        float4 o;
        o.x = gru_elem(Ir.x, Iz.x, In.x, Hr.x, Hz.x, Hn.x, h.x);
        o.y = gru_elem(Ir.y, Iz.y, In.y, Hr.y, Hz.y, Hn.y, h.y);
        o.z = gru_elem(Ir.z, Iz.z, In.z, Hr.z, Hz.z, Hn.z, h.z);
        o.w = gru_elem(Ir.w, Iz.w, In.w, Hr.w, Hz.w, Hn.w, h.w);
        size_t off = (size_t)b * HID + q;
        *(float4*)(g_h1 + off) = o;
        split_store4h(o, off, g_h1p[0], g_h1p[1]);
        *(float4*)&hs[wr][q] = o;
    }
    __syncthreads();

    // ---- phase 2: logits + log_softmax + argmax ----
    int na = lane, nb = lane + 32;
    const float4* w0p = (const float4*)(w_out + na * HID);
    const float4* w1p = (const float4*)(w_out + nb * HID);
    const float4* hp = (const float4*)&hs[wr][0];
    float acc0 = 0.f, acc1 = 0.f;
#pragma unroll 8
    for (int k = 0; k < HID / 4; k++) {
        float4 hv = hp[k];
        float4 w0 = w0p[k];
        acc0 += hv.x * w0.x + hv.y * w0.y + hv.z * w0.z + hv.w * w0.w;
        float4 w1 = w1p[k];
        acc1 += hv.x * w1.x + hv.y * w1.y + hv.z * w1.z + hv.w * w1.w;
    }
    float l0 = acc0 + b_out[na];
    float l1 = acc1 + b_out[nb];

    float mx = fmaxf(l0, l1);
#pragma unroll
    for (int off = 16; off; off >>= 1) mx = fmaxf(mx, __shfl_xor_sync(0xffffffffu, mx, off));
    float se = expf(l0 - mx) + expf(l1 - mx);
#pragma unroll
    for (int off = 16; off; off >>= 1) se += __shfl_xor_sync(0xffffffffu, se, off);
    float lse = logf(se);

    float* yr = Y + ((size_t)s * BB + b) * ATOM;
    yr[na] = l0 - mx - lse;
    yr[nb] = l1 - mx - lse;

    float v; int ix;
    if (l0 >= l1) { v = l0; ix = na; } else { v = l1; ix = nb; }
#pragma unroll
    for (int off = 16; off; off >>= 1) {
        float ov = __shfl_xor_sync(0xffffffffu, v, off);
        int oi = __shfl_xor_sync(0xffffffffu, ix, off);
        if (ov > v || (ov == v && oi < ix)) { v = ov; ix = oi; }
    }
    if (lane == 0) g_p[b] = ix;
}

// ---------------- launch ---------------------------------------------------
extern "C" void kernel_launch(void* const* d_in, const int* in_sizes, int n_in,
                              void* d_out, int out_size) {
    const float* enc   = (const float*)d_in[0];
    const float* emb   = (const float*)d_in[1];
    const float* w_h0  = (const float*)d_in[2];
    const float* b_h0  = (const float*)d_in[3];
    const float* w_ih0 = (const float*)d_in[4];
    const float* w_hh0 = (const float*)d_in[5];
    const float* b_ih0 = (const float*)d_in[6];
    const float* b_hh0 = (const float*)d_in[7];
    const float* w_ih1 = (const float*)d_in[8];
    const float* w_hh1 = (const float*)d_in[9];
    const float* b_ih1 = (const float*)d_in[10];
    const float* b_hh1 = (const float*)d_in[11];
    const float* w_out = (const float*)d_in[12];
    const float* b_out = (const float*)d_in[13];
    float* Y = (float*)d_out;

    float *h0p, *h1p, *G1p, *G2p;
    unsigned short *h0l, *h1l, *w0l, *w1l, *w2l;
    cudaGetSymbolAddress((void**)&h0p, g_h0);
    cudaGetSymbolAddress((void**)&h1p, g_h1);
    cudaGetSymbolAddress((void**)&G1p, g_G1);
    cudaGetSymbolAddress((void**)&G2p, g_G2);
    cudaGetSymbolAddress((void**)&h0l, g_h0p);
    cudaGetSymbolAddress((void**)&h1l, g_h1p);
    cudaGetSymbolAddress((void**)&w0l, g_w0p);
    cudaGetSymbolAddress((void**)&w1l, g_w1p);
    cudaGetSymbolAddress((void**)&w2l, g_w2p);

    const int HN = BB * HID;       // h limb plane size
    const int WN = H3 * HID;       // weight limb plane size

    const int smem_sz = NSTAGE * BUF_BYTES;   // 3 * 65536 = 196608
    cudaFuncSetAttribute(gemm_mma_kernel, cudaFuncAttributeMaxDynamicSharedMemorySize, smem_sz);

    initp_kernel<<<BB / 256, 256>>>();
    table_kernel<<<dim3(H3 / 256, ATOM), 256>>>(emb, w_ih0, b_ih0);

    // split weights into fp16 limbs
    split2_kernel<<<(WN + 255) / 256, 256>>>(w_hh0, w0l, w0l + WN, WN);
    split2_kernel<<<(WN + 255) / 256, 256>>>(w_ih1, w1l, w1l + WN, WN);
    split2_kernel<<<(WN + 255) / 256, 256>>>(w_hh1, w2l, w2l + WN, WN);

    // h_init = tanh(enc @ w_h0.T + b_h0) -> g_h0 / g_h1, then limb-split
    gemm_init_kernel<<<dim3((2 * HID) / BNT, BB / BMT), 256>>>(enc, w_h0, b_h0, ENC);
    split2_kernel<<<(HN + 255) / 256, 256>>>(h0p, h0l, h0l + HN, HN);
    split2_kernel<<<(HN + 255) / 256, 256>>>(h1p, h1l, h1l + HN, HN);

    dim3 grid1(H3 / 128, BB / 128, 1);        // 12 x 64 x 1
    dim3 grid2(H3 / 128, BB / 128, 2);        // 12 x 64 x 2 (merged gh0/gh1)
    int gate_blocks = BB * (HID / 4) / 256;   // 4096

    for (int s = 0; s < STEPS; s++) {
        // z=0: gh0 = h0 @ w_hh0.T + b_hh0 ; z=1: gh1 = h1_old @ w_hh1.T + b_hh1
        gemm_mma_kernel<<<grid2, NT, smem_sz>>>(
            h0l, w0l, b_hh0, G1p,
            h1l, w2l, b_hh1, G2p, HN, WN);
        gate0_kernel<<<gate_blocks, 256>>>();
        // gi1 = h0_new @ w_ih1.T + b_ih1
        gemm_mma_kernel<<<grid1, NT, smem_sz>>>(
            h0l, w1l, b_ih1, G1p,
            h0l, w1l, b_ih1, G1p, HN, WN);
        gate1out_kernel<<<BB / 8, 256>>>(w_out, b_out, Y, s);
    }
}

// round 9
// speedup vs baseline: 1.0047x; 1.0047x over previous
#include <cuda_runtime.h>
#include <cuda_fp16.h>
#include <math.h>
#include <stdint.h>

#define MSLQ 64
#define BSQ  128
#define BB   8192      // MSL*BS
#define ENC  1024
#define HID  512
#define H3   1536      // 3*HID
#define EMBQ 50
#define ATOM 64
#define STEPS 49
#define SOS  1

#define LIMB_SCALE 2048.0f
#define INV_LIMB   (1.0f / 2048.0f)

// ---------------- scratch (device globals: no runtime allocation) ----------
__device__ float g_h0[BB * HID];
__device__ float g_h1[BB * HID];
__device__ float g_G1[BB * H3];
__device__ float g_G2[BB * H3];
__device__ float g_T0[ATOM * H3];
__device__ int   g_p[BB];

// fp16 limb planes (limb1 pre-scaled by 2048)
__device__ __align__(256) unsigned short g_h0p[2][BB * HID];
__device__ __align__(256) unsigned short g_h1p[2][BB * HID];
__device__ __align__(256) unsigned short g_w0p[2][H3 * HID];   // w_hh0 limbs
__device__ __align__(256) unsigned short g_w1p[2][H3 * HID];   // w_ih1 limbs
__device__ __align__(256) unsigned short g_w2p[2][H3 * HID];   // w_hh1 limbs

// ---------------- small helpers -------------------------------------------
__device__ __forceinline__ float sigf(float x) { return 1.0f / (1.0f + expf(-x)); }

__device__ __forceinline__ float gru_elem(float ti, float tz, float tn,
                                          float gr, float gz, float gn, float h) {
    float r = sigf(ti + gr);
    float z = sigf(tz + gz);
    float n = tanhf(tn + r * gn);
    return (1.0f - z) * n + z * h;
}

__device__ __forceinline__ uint32_t smem_u32(const void* p) {
    uint32_t a;
    asm("{ .reg .u64 t; cvta.to.shared.u64 t, %1; cvt.u32.u64 %0, t; }" : "=r"(a) : "l"(p));
    return a;
}

#define SWZ(o) ((o) ^ (((o) >> 3) & 0x70))

__device__ __forceinline__ void cp16(uint32_t dst, const void* src) {
    asm volatile("cp.async.cg.shared.global [%0], [%1], 16;" :: "r"(dst), "l"(src) : "memory");
}

__device__ __forceinline__ void ldsm4(uint32_t* r, uint32_t addr) {
    asm volatile("ldmatrix.sync.aligned.m8n8.x4.shared.b16 {%0,%1,%2,%3}, [%4];"
                 : "=r"(r[0]), "=r"(r[1]), "=r"(r[2]), "=r"(r[3]) : "r"(addr));
}

// fp32-accumulate HMMA (main product)
__device__ __forceinline__ void mma16816h(float* c, const uint32_t* a, const uint32_t* b) {
    asm volatile("mma.sync.aligned.m16n8k16.row.col.f32.f16.f16.f32 "
                 "{%0,%1,%2,%3}, {%4,%5,%6,%7}, {%8,%9}, {%0,%1,%2,%3};"
                 : "+f"(c[0]), "+f"(c[1]), "+f"(c[2]), "+f"(c[3])
                 : "r"(a[0]), "r"(a[1]), "r"(a[2]), "r"(a[3]), "r"(b[0]), "r"(b[1]));
}

// fp16-accumulate HMMA (correction products; d/c are 2 regs = 4 halves)
__device__ __forceinline__ void mma16816hh(uint32_t* c, const uint32_t* a, const uint32_t* b) {
    asm volatile("mma.sync.aligned.m16n8k16.row.col.f16.f16.f16.f16 "
                 "{%0,%1}, {%2,%3,%4,%5}, {%6,%7}, {%0,%1};"
                 : "+r"(c[0]), "+r"(c[1])
                 : "r"(a[0]), "r"(a[1]), "r"(a[2]), "r"(a[3]), "r"(b[0]), "r"(b[1]));
}

// ---------------- fp16 2-limb split (limb1 scaled by 2048) ----------------
__device__ __forceinline__ void split1h(float v, unsigned short& s0, unsigned short& s1) {
    __half t0 = __float2half_rn(v);
    float r = (v - __half2float(t0)) * LIMB_SCALE;
    __half t1 = __float2half_rn(r);
    s0 = __half_as_ushort(t0);
    s1 = __half_as_ushort(t1);
}

__device__ __forceinline__ void split_store4h(float4 o, size_t off,
                                              unsigned short* P0, unsigned short* P1) {
    float v[4] = {o.x, o.y, o.z, o.w};
    unsigned short a0[4], a1[4];
#pragma unroll
    for (int j = 0; j < 4; j++) split1h(v[j], a0[j], a1[j]);
    *(ushort4*)(P0 + off) = make_ushort4(a0[0], a0[1], a0[2], a0[3]);
    *(ushort4*)(P1 + off) = make_ushort4(a1[0], a1[1], a1[2], a1[3]);
}

__global__ void split2_kernel(const float* __restrict__ x,
                              unsigned short* __restrict__ p0,
                              unsigned short* __restrict__ p1, int n) {
    int i = blockIdx.x * blockDim.x + threadIdx.x;
    if (i >= n) return;
    unsigned short s0, s1;
    split1h(x[i], s0, s1);
    p0[i] = s0; p1[i] = s1;
}

// ---------------- init p = SOS --------------------------------------------
__global__ void initp_kernel() {
    int i = blockIdx.x * blockDim.x + threadIdx.x;
    if (i < BB) g_p[i] = SOS;
}

// ---------------- T0[a][n] = b_ih0[n] + sum_k emb[a][k] * w_ih0[n][k] ------
__global__ void table_kernel(const float* __restrict__ emb,
                             const float* __restrict__ w_ih0,
                             const float* __restrict__ b_ih0) {
    int n = blockIdx.x * blockDim.x + threadIdx.x;
    int a = blockIdx.y;
    if (n >= H3) return;
    float acc = b_ih0[n];
    const float* er = emb + a * EMBQ;
    const float* wr = w_ih0 + n * EMBQ;
#pragma unroll
    for (int k = 0; k < EMBQ; k++) acc += er[k] * wr[k];
    g_T0[a * H3 + n] = acc;
}

// ---------------- fp32 SIMT GEMM (init only): tanh + split to h0/h1 -------
#define BMT 128
#define BNT 128
#define BKT 16

__device__ __forceinline__ unsigned long long splat2(float a) {
    unsigned long long d;
    unsigned int u = __float_as_uint(a);
    asm("mov.b64 %0, {%1, %1};" : "=l"(d) : "r"(u));
    return d;
}
__device__ __forceinline__ void fma2(unsigned long long& c, unsigned long long a, unsigned long long b) {
    asm("fma.rn.f32x2 %0, %1, %2, %0;" : "+l"(c) : "l"(a), "l"(b));
}
__device__ __forceinline__ float2 unpack2(unsigned long long c) {
    unsigned int lo, hi;
    asm("mov.b64 {%0, %1}, %2;" : "=r"(lo), "=r"(hi) : "l"(c));
    float2 f; f.x = __uint_as_float(lo); f.y = __uint_as_float(hi);
    return f;
}

__global__ __launch_bounds__(256, 2) void gemm_init_kernel(
    const float* __restrict__ A, const float* __restrict__ W,
    const float* __restrict__ bias, int K)
{
    __shared__ float As[BKT][BMT];
    __shared__ float Ws[BKT][BNT];

    int tid = threadIdx.x;
    int m0 = blockIdx.y * BMT;
    int n0 = blockIdx.x * BNT;
    int tr = tid >> 4;
    int tc = tid & 15;

    unsigned long long acc[8][4];
#pragma unroll
    for (int i = 0; i < 8; i++)
#pragma unroll
        for (int j = 0; j < 4; j++) acc[i][j] = 0ull;

    for (int kt = 0; kt < K; kt += BKT) {
#pragma unroll
        for (int l = 0; l < 2; l++) {
            int fid = tid + l * 256;
            int r = fid >> 2;
            int c4 = (fid & 3) * 4;
            float4 va = *(const float4*)(A + (size_t)(m0 + r) * K + kt + c4);
            As[c4 + 0][r] = va.x; As[c4 + 1][r] = va.y;
            As[c4 + 2][r] = va.z; As[c4 + 3][r] = va.w;
            float4 vw = *(const float4*)(W + (size_t)(n0 + r) * K + kt + c4);
            Ws[c4 + 0][r] = vw.x; Ws[c4 + 1][r] = vw.y;
            Ws[c4 + 2][r] = vw.z; Ws[c4 + 3][r] = vw.w;
        }
        __syncthreads();
#pragma unroll
        for (int k = 0; k < BKT; k++) {
            float4 a0 = *(const float4*)&As[k][tr * 8];
            float4 a1 = *(const float4*)&As[k][tr * 8 + 4];
            float av[8] = {a0.x, a0.y, a0.z, a0.w, a1.x, a1.y, a1.z, a1.w};
            const unsigned long long* wp = (const unsigned long long*)&Ws[k][0];
            unsigned long long bv[4];
#pragma unroll
            for (int j = 0; j < 4; j++) bv[j] = wp[tc * 4 + j];
#pragma unroll
            for (int i = 0; i < 8; i++) {
                unsigned long long as = splat2(av[i]);
#pragma unroll
                for (int j = 0; j < 4; j++) fma2(acc[i][j], as, bv[j]);
            }
        }
        __syncthreads();
    }

    int nb = n0 + tc * 8;
    float bb[8];
#pragma unroll
    for (int j = 0; j < 8; j++) bb[j] = bias[nb + j];

#pragma unroll
    for (int i = 0; i < 8; i++) {
        int m = m0 + tr * 8 + i;
#pragma unroll
        for (int jp = 0; jp < 4; jp++) {
            float2 f = unpack2(acc[i][jp]);
            float v0 = tanhf(f.x + bb[2 * jp]);
            float v1 = tanhf(f.y + bb[2 * jp + 1]);
            int n = nb + 2 * jp;
            if (n < HID) {
                g_h0[m * HID + n] = v0;
                g_h0[m * HID + n + 1] = v1;
            } else {
                g_h1[m * HID + n - HID] = v0;
                g_h1[m * HID + n - HID + 1] = v1;
            }
        }
    }
}

// ---------------- mma.sync fp16x3 GEMM: C = bias + A*W^T (fp32-emulated) ---
// 256 threads, 8 warps in 2x4 grid, warp tile 64x32; CTA tile 128x128.
// Main product a0*b0 -> fp32 acc; corrections a0*b1s + a1s*b0 -> fp16 acc.
// C = acc0 + acc1/2048 + bias. blockIdx.z selects operand set.
#define KCH 64
#define NCHUNK (HID / KCH)       // 8
#define PART_BYTES (128 * 128)   // 128 rows x 128B (one limb, one chunk)
#define BUF_BYTES (4 * PART_BYTES)   // A0,A1,B0,B1
#define NSTAGE 3
#define NT 256

__global__ __launch_bounds__(NT, 1) void gemm_mma_kernel(
    const unsigned short* __restrict__ Aa, const unsigned short* __restrict__ Wa,
    const float* __restrict__ biasa, float* __restrict__ Ca,
    const unsigned short* __restrict__ Ab, const unsigned short* __restrict__ Wb,
    const float* __restrict__ biasb, float* __restrict__ Cb,
    int hplane, int wplane)
{
    extern __shared__ __align__(1024) char smem[];
    const uint32_t sb = smem_u32(smem);
    const int tid = threadIdx.x;
    const int wid = tid >> 5;
    const int lane = tid & 31;
    const int n0 = blockIdx.x * 128;
    const int m0 = blockIdx.y * 128;

    const unsigned short* A = (blockIdx.z == 0) ? Aa : Ab;
    const unsigned short* W = (blockIdx.z == 0) ? Wa : Wb;
    const float* bias        = (blockIdx.z == 0) ? biasa : biasb;
    float* C                 = (blockIdx.z == 0) ? Ca : Cb;

    const int wm = wid & 1;          // 2 warp-rows (64 m each)
    const int wn = wid >> 1;         // 4 warp-cols (32 n each)
    const int mW = wm * 64;
    const int nW = wn * 32;

    // ldmatrix per-thread address components
    const int a_row = ((lane >> 3) & 1) * 8 + (lane & 7);
    const int a_hb  = (lane >> 4) * 16;          // k-half byte for A
    const int b_row = ((lane >> 4) & 1) * 8 + (lane & 7);
    const int b_hb  = ((lane >> 3) & 1) * 16;    // k-half byte for B

    const char* Ap[2];
    const char* Bp[2];
#pragma unroll
    for (int p = 0; p < 2; p++) {
        Ap[p] = (const char*)(A + (size_t)p * hplane);
        Bp[p] = (const char*)(W + (size_t)p * wplane);
    }

    float    c0[4][4][4];        // fp32 main accumulators
    uint32_t c1[4][4][2];        // fp16x2 correction accumulators
#pragma unroll
    for (int i = 0; i < 4; i++)
#pragma unroll
        for (int j = 0; j < 4; j++) {
#pragma unroll
            for (int q = 0; q < 4; q++) c0[i][j][q] = 0.f;
            c1[i][j][0] = 0u; c1[i][j][1] = 0u;
        }

    auto load_chunk = [&](int c) {
        int buf = c % NSTAGE;
        uint32_t base = sb + buf * BUF_BYTES;
#pragma unroll
        for (int p = 0; p < 2; p++) {
            const char* srcA = Ap[p] + (size_t)m0 * 1024 + c * 128;   // row stride 512*2B
            uint32_t da = base + p * PART_BYTES;
#pragma unroll
            for (int i = tid; i < 1024; i += NT) {
                int row = i >> 3, seg = (i & 7) << 4;
                cp16(da + SWZ(row * 128 + seg), srcA + (size_t)row * 1024 + seg);
            }
            const char* srcB = Bp[p] + (size_t)n0 * 1024 + c * 128;
            uint32_t db = base + (2 + p) * PART_BYTES;
#pragma unroll
            for (int i = tid; i < 1024; i += NT) {
                int row = i >> 3, seg = (i & 7) << 4;
                cp16(db + SWZ(row * 128 + seg), srcB + (size_t)row * 1024 + seg);
            }
        }
        asm volatile("cp.async.commit_group;" ::: "memory");
    };

    load_chunk(0);
    load_chunk(1);

    for (int c = 0; c < NCHUNK; c++) {
        if (c + 1 < NCHUNK) {
            asm volatile("cp.async.wait_group 1;" ::: "memory");   // chunk c arrived
        } else {
            asm volatile("cp.async.wait_group 0;" ::: "memory");
        }
        __syncthreads();   // all warps finished consuming chunk c-1; chunk c visible
        if (c + 2 < NCHUNK) load_chunk(c + 2);

        uint32_t base = sb + (c % NSTAGE) * BUF_BYTES;

#pragma unroll
        for (int kk = 0; kk < 4; kk++) {
            const int k0b = kk * 32;
            uint32_t a0f[4][4], a1f[4][4], b0f[8], b1f[8];

            auto ldA = [&](int p, uint32_t (*af)[4]) {
                uint32_t pb = base + p * PART_BYTES;
#pragma unroll
                for (int mi = 0; mi < 4; mi++) {
                    int row = mW + mi * 16 + a_row;
                    ldsm4(af[mi], pb + SWZ(row * 128 + k0b + a_hb));
                }
            };
            auto ldB = [&](int p, uint32_t* bf) {
                uint32_t pb = base + (2 + p) * PART_BYTES;
#pragma unroll
                for (int j = 0; j < 2; j++) {
                    int row = nW + j * 16 + b_row;
                    ldsm4(bf + j * 4, pb + SWZ(row * 128 + k0b + b_hb));
                }
            };

            ldA(0, a0f); ldB(0, b0f);
            // main product: fp32 accumulate
#pragma unroll
            for (int mi = 0; mi < 4; mi++)
#pragma unroll
                for (int ni = 0; ni < 4; ni++)
                    mma16816h(c0[mi][ni], a0f[mi], b0f + ni * 2);
            // corrections: fp16 accumulate
            ldB(1, b1f);
#pragma unroll
            for (int mi = 0; mi < 4; mi++)
#pragma unroll
                for (int ni = 0; ni < 4; ni++)
                    mma16816hh(c1[mi][ni], a0f[mi], b1f + ni * 2);
            ldA(1, a1f);
#pragma unroll
            for (int mi = 0; mi < 4; mi++)
#pragma unroll
                for (int ni = 0; ni < 4; ni++)
                    mma16816hh(c1[mi][ni], a1f[mi], b0f + ni * 2);
        }
    }

    // ---- epilogue: combine limbs + bias, direct stores ----
    const int tr = lane >> 2;
    const int tc2 = (lane & 3) * 2;
#pragma unroll
    for (int mi = 0; mi < 4; mi++) {
        int row = m0 + mW + mi * 16 + tr;
#pragma unroll
        for (int ni = 0; ni < 4; ni++) {
            int col = n0 + nW + ni * 8 + tc2;
            float bx = bias[col], by = bias[col + 1];
            float2 e0 = __half22float2(*reinterpret_cast<__half2*>(&c1[mi][ni][0]));
            float2 e1 = __half22float2(*reinterpret_cast<__half2*>(&c1[mi][ni][1]));
            float2 v0;
            v0.x = c0[mi][ni][0] + e0.x * INV_LIMB + bx;
            v0.y = c0[mi][ni][1] + e0.y * INV_LIMB + by;
            *(float2*)&C[(size_t)row * H3 + col] = v0;
            float2 v1;
            v1.x = c0[mi][ni][2] + e1.x * INV_LIMB + bx;
            v1.y = c0[mi][ni][3] + e1.y * INV_LIMB + by;
            *(float2*)&C[(size_t)(row + 8) * H3 + col] = v1;
        }
    }
}

// ---------------- gate0 (gi from table, gh in G1; emit h0 + limbs) --------
__global__ __launch_bounds__(256) void gate0_kernel() {
    int idx = blockIdx.x * blockDim.x + threadIdx.x;
    int b = idx >> 7;
    int q = (idx & 127) << 2;
    int p = g_p[b];
    const float* T = g_T0 + p * H3;
    float4 Tr = *(const float4*)(T + q);
    float4 Tz = *(const float4*)(T + HID + q);
    float4 Tn = *(const float4*)(T + 2 * HID + q);
    const float* Gb = g_G1 + (size_t)b * H3;
    float4 Gr = *(const float4*)(Gb + q);
    float4 Gz = *(const float4*)(Gb + HID + q);
    float4 Gn = *(const float4*)(Gb + 2 * HID + q);
    float4 h = *(const float4*)(g_h0 + b * HID + q);
    float4 o;
    o.x = gru_elem(Tr.x, Tz.x, Tn.x, Gr.x, Gz.x, Gn.x, h.x);
    o.y = gru_elem(Tr.y, Tz.y, Tn.y, Gr.y, Gz.y, Gn.y, h.y);
    o.z = gru_elem(Tr.z, Tz.z, Tn.z, Gr.z, Gz.z, Gn.z, h.z);
    o.w = gru_elem(Tr.w, Tz.w, Tn.w, Gr.w, Gz.w, Gn.w, h.w);
    size_t off = (size_t)b * HID + q;
    *(float4*)(g_h0 + off) = o;
    split_store4h(o, off, g_h0p[0], g_h0p[1]);
}

// ---------------- fused gate1 + output ------------------------------------
__global__ __launch_bounds__(256) void gate1out_kernel(const float* __restrict__ w_out,
                                                       const float* __restrict__ b_out,
                                                       float* __restrict__ Y, int s) {
    __shared__ float hs[8][HID];
    int tid = threadIdx.x;
    int wr = tid >> 5;
    int lane = tid & 31;
    int b0 = blockIdx.x * 8;
    int b = b0 + wr;

    // ---- phase 1: gate (each thread: 16 cols of its row) ----
    const float* Gi = g_G1 + (size_t)b * H3;
    const float* Gh = g_G2 + (size_t)b * H3;
    int q0 = lane * 16;
#pragma unroll
    for (int j = 0; j < 4; j++) {
        int q = q0 + j * 4;
        float4 Ir = *(const float4*)(Gi + q);
        float4 Iz = *(const float4*)(Gi + HID + q);
        float4 In = *(const float4*)(Gi + 2 * HID + q);
        float4 Hr = *(const float4*)(Gh + q);
        float4 Hz = *(const float4*)(Gh + HID + q);
        float4 Hn = *(const float4*)(Gh + 2 * HID + q);
        float4 h = *(const float4*)(g_h1 + (size_t)b * HID + q);
        float4 o;
        o.x = gru_elem(Ir.x, Iz.x, In.x, Hr.x, Hz.x, Hn.x, h.x);
        o.y = gru_elem(Ir.y, Iz.y, In.y, Hr.y, Hz.y, Hn.y, h.y);
        o.z = gru_elem(Ir.z, Iz.z, In.z, Hr.z, Hz.z, Hn.z, h.z);
        o.w = gru_elem(Ir.w, Iz.w, In.w, Hr.w, Hz.w, Hn.w, h.w);
        size_t off = (size_t)b * HID + q;
        *(float4*)(g_h1 + off) = o;
        split_store4h(o, off, g_h1p[0], g_h1p[1]);
        *(float4*)&hs[wr][q] = o;
    }
    __syncthreads();

    // ---- phase 2: logits + log_softmax + argmax ----
    int na = lane, nb = lane + 32;
    const float4* w0p = (const float4*)(w_out + na * HID);
    const float4* w1p = (const float4*)(w_out + nb * HID);
    const float4* hp = (const float4*)&hs[wr][0];
    float acc0 = 0.f, acc1 = 0.f;
#pragma unroll 8
    for (int k = 0; k < HID / 4; k++) {
        float4 hv = hp[k];
        float4 w0 = w0p[k];
        acc0 += hv.x * w0.x + hv.y * w0.y + hv.z * w0.z + hv.w * w0.w;
        float4 w1 = w1p[k];
        acc1 += hv.x * w1.x + hv.y * w1.y + hv.z * w1.z + hv.w * w1.w;
    }
    float l0 = acc0 + b_out[na];
    float l1 = acc1 + b_out[nb];

    float mx = fmaxf(l0, l1);
#pragma unroll
    for (int off = 16; off; off >>= 1) mx = fmaxf(mx, __shfl_xor_sync(0xffffffffu, mx, off));
    float se = expf(l0 - mx) + expf(l1 - mx);
#pragma unroll
    for (int off = 16; off; off >>= 1) se += __shfl_xor_sync(0xffffffffu, se, off);
    float lse = logf(se);

    float* yr = Y + ((size_t)s * BB + b) * ATOM;
    yr[na] = l0 - mx - lse;
    yr[nb] = l1 - mx - lse;

    float v; int ix;
    if (l0 >= l1) { v = l0; ix = na; } else { v = l1; ix = nb; }
#pragma unroll
    for (int off = 16; off; off >>= 1) {
        float ov = __shfl_xor_sync(0xffffffffu, v, off);
        int oi = __shfl_xor_sync(0xffffffffu, ix, off);
        if (ov > v || (ov == v && oi < ix)) { v = ov; ix = oi; }
    }
    if (lane == 0) g_p[b] = ix;
}

// ---------------- launch ---------------------------------------------------
extern "C" void kernel_launch(void* const* d_in, const int* in_sizes, int n_in,
                              void* d_out, int out_size) {
    const float* enc   = (const float*)d_in[0];
    const float* emb   = (const float*)d_in[1];
    const float* w_h0  = (const float*)d_in[2];
    const float* b_h0  = (const float*)d_in[3];
    const float* w_ih0 = (const float*)d_in[4];
    const float* w_hh0 = (const float*)d_in[5];
    const float* b_ih0 = (const float*)d_in[6];
    const float* b_hh0 = (const float*)d_in[7];
    const float* w_ih1 = (const float*)d_in[8];
    const float* w_hh1 = (const float*)d_in[9];
    const float* b_ih1 = (const float*)d_in[10];
    const float* b_hh1 = (const float*)d_in[11];
    const float* w_out = (const float*)d_in[12];
    const float* b_out = (const float*)d_in[13];
    float* Y = (float*)d_out;

    float *h0p, *h1p, *G1p, *G2p;
    unsigned short *h0l, *h1l, *w0l, *w1l, *w2l;
    cudaGetSymbolAddress((void**)&h0p, g_h0);
    cudaGetSymbolAddress((void**)&h1p, g_h1);
    cudaGetSymbolAddress((void**)&G1p, g_G1);
    cudaGetSymbolAddress((void**)&G2p, g_G2);
    cudaGetSymbolAddress((void**)&h0l, g_h0p);
    cudaGetSymbolAddress((void**)&h1l, g_h1p);
    cudaGetSymbolAddress((void**)&w0l, g_w0p);
    cudaGetSymbolAddress((void**)&w1l, g_w1p);
    cudaGetSymbolAddress((void**)&w2l, g_w2p);

    const int HN = BB * HID;       // h limb plane size
    const int WN = H3 * HID;       // weight limb plane size

    const int smem_sz = NSTAGE * BUF_BYTES;   // 3 * 65536 = 196608
    cudaFuncSetAttribute(gemm_mma_kernel, cudaFuncAttributeMaxDynamicSharedMemorySize, smem_sz);

    initp_kernel<<<BB / 256, 256>>>();
    table_kernel<<<dim3(H3 / 256, ATOM), 256>>>(emb, w_ih0, b_ih0);

    // split weights into fp16 limbs
    split2_kernel<<<(WN + 255) / 256, 256>>>(w_hh0, w0l, w0l + WN, WN);
    split2_kernel<<<(WN + 255) / 256, 256>>>(w_ih1, w1l, w1l + WN, WN);
    split2_kernel<<<(WN + 255) / 256, 256>>>(w_hh1, w2l, w2l + WN, WN);

    // h_init = tanh(enc @ w_h0.T + b_h0) -> g_h0 / g_h1, then limb-split
    gemm_init_kernel<<<dim3((2 * HID) / BNT, BB / BMT), 256>>>(enc, w_h0, b_h0, ENC);
    split2_kernel<<<(HN + 255) / 256, 256>>>(h0p, h0l, h0l + HN, HN);
    split2_kernel<<<(HN + 255) / 256, 256>>>(h1p, h1l, h1l + HN, HN);

    dim3 grid1(H3 / 128, BB / 128, 1);        // 12 x 64 x 1
    dim3 grid2(H3 / 128, BB / 128, 2);        // 12 x 64 x 2 (merged gh0/gh1)
    int gate_blocks = BB * (HID / 4) / 256;   // 4096

    for (int s = 0; s < STEPS; s++) {
        // z=0: gh0 = h0 @ w_hh0.T + b_hh0 ; z=1: gh1 = h1_old @ w_hh1.T + b_hh1
        gemm_mma_kernel<<<grid2, NT, smem_sz>>>(
            h0l, w0l, b_hh0, G1p,
            h1l, w2l, b_hh1, G2p, HN, WN);
        gate0_kernel<<<gate_blocks, 256>>>();
        // gi1 = h0_new @ w_ih1.T + b_ih1
        gemm_mma_kernel<<<grid1, NT, smem_sz>>>(
            h0l, w1l, b_ih1, G1p,
            h0l, w1l, b_ih1, G1p, HN, WN);
        gate1out_kernel<<<BB / 8, 256>>>(w_out, b_out, Y, s);
    }
}

// round 11
// speedup vs baseline: 1.0373x; 1.0324x over previous
#include <cuda_runtime.h>
#include <cuda_fp16.h>
#include <math.h>
#include <stdint.h>

#define MSLQ 64
#define BSQ  128
#define BB   8192      // MSL*BS
#define ENC  1024
#define HID  512
#define H3   1536      // 3*HID
#define EMBQ 50
#define ATOM 64
#define STEPS 49
#define SOS  1

#define LIMB_SCALE 2048.0f
#define INV_LIMB   (1.0f / 2048.0f)

// ---------------- scratch (device globals: no runtime allocation) ----------
__device__ float g_h0[BB * HID];
__device__ float g_h1[BB * HID];
__device__ float g_G1[BB * H3];   // gh0 out -> gate0 in
__device__ float g_G2[BB * H3];   // gh1 out -> gate1out in
__device__ float g_G3[BB * H3];   // gi1 out -> gate1out in (separate: breaks WAR vs gh0)
__device__ float g_T0[ATOM * H3];
__device__ int   g_p[BB];

// fp16 limb planes (limb1 pre-scaled by 2048)
__device__ __align__(256) unsigned short g_h0p[2][BB * HID];
__device__ __align__(256) unsigned short g_h1p[2][BB * HID];
__device__ __align__(256) unsigned short g_w0p[2][H3 * HID];   // w_hh0 limbs
__device__ __align__(256) unsigned short g_w1p[2][H3 * HID];   // w_ih1 limbs
__device__ __align__(256) unsigned short g_w2p[2][H3 * HID];   // w_hh1 limbs

// ---------------- small helpers -------------------------------------------
__device__ __forceinline__ float sigf(float x) { return 1.0f / (1.0f + expf(-x)); }

__device__ __forceinline__ float gru_elem(float ti, float tz, float tn,
                                          float gr, float gz, float gn, float h) {
    float r = sigf(ti + gr);
    float z = sigf(tz + gz);
    float n = tanhf(tn + r * gn);
    return (1.0f - z) * n + z * h;
}

__device__ __forceinline__ uint32_t smem_u32(const void* p) {
    uint32_t a;
    asm("{ .reg .u64 t; cvta.to.shared.u64 t, %1; cvt.u32.u64 %0, t; }" : "=r"(a) : "l"(p));
    return a;
}

#define SWZ(o) ((o) ^ (((o) >> 3) & 0x70))

__device__ __forceinline__ void cp16(uint32_t dst, const void* src) {
    asm volatile("cp.async.cg.shared.global [%0], [%1], 16;" :: "r"(dst), "l"(src) : "memory");
}

__device__ __forceinline__ void ldsm4(uint32_t* r, uint32_t addr) {
    asm volatile("ldmatrix.sync.aligned.m8n8.x4.shared.b16 {%0,%1,%2,%3}, [%4];"
                 : "=r"(r[0]), "=r"(r[1]), "=r"(r[2]), "=r"(r[3]) : "r"(addr));
}

// fp32-accumulate HMMA (main product)
__device__ __forceinline__ void mma16816h(float* c, const uint32_t* a, const uint32_t* b) {
    asm volatile("mma.sync.aligned.m16n8k16.row.col.f32.f16.f16.f32 "
                 "{%0,%1,%2,%3}, {%4,%5,%6,%7}, {%8,%9}, {%0,%1,%2,%3};"
                 : "+f"(c[0]), "+f"(c[1]), "+f"(c[2]), "+f"(c[3])
                 : "r"(a[0]), "r"(a[1]), "r"(a[2]), "r"(a[3]), "r"(b[0]), "r"(b[1]));
}

// fp16-accumulate HMMA (correction products; d/c are 2 regs = 4 halves)
__device__ __forceinline__ void mma16816hh(uint32_t* c, const uint32_t* a, const uint32_t* b) {
    asm volatile("mma.sync.aligned.m16n8k16.row.col.f16.f16.f16.f16 "
                 "{%0,%1}, {%2,%3,%4,%5}, {%6,%7}, {%0,%1};"
                 : "+r"(c[0]), "+r"(c[1])
                 : "r"(a[0]), "r"(a[1]), "r"(a[2]), "r"(a[3]), "r"(b[0]), "r"(b[1]));
}

// ---------------- fp16 2-limb split (limb1 scaled by 2048) ----------------
__device__ __forceinline__ void split1h(float v, unsigned short& s0, unsigned short& s1) {
    __half t0 = __float2half_rn(v);
    float r = (v - __half2float(t0)) * LIMB_SCALE;
    __half t1 = __float2half_rn(r);
    s0 = __half_as_ushort(t0);
    s1 = __half_as_ushort(t1);
}

__device__ __forceinline__ void split_store4h(float4 o, size_t off,
                                              unsigned short* P0, unsigned short* P1) {
    float v[4] = {o.x, o.y, o.z, o.w};
    unsigned short a0[4], a1[4];
#pragma unroll
    for (int j = 0; j < 4; j++) split1h(v[j], a0[j], a1[j]);
    *(ushort4*)(P0 + off) = make_ushort4(a0[0], a0[1], a0[2], a0[3]);
    *(ushort4*)(P1 + off) = make_ushort4(a1[0], a1[1], a1[2], a1[3]);
}

// dual split: blockIdx.y selects source/dest pair (merged launches)
__global__ void split2_dual_kernel(const float* __restrict__ x0,
                                   unsigned short* __restrict__ a0,
                                   unsigned short* __restrict__ a1,
                                   const float* __restrict__ x1,
                                   unsigned short* __restrict__ b0,
                                   unsigned short* __restrict__ b1, int n) {
    int i = blockIdx.x * blockDim.x + threadIdx.x;
    if (i >= n) return;
    const float* x = blockIdx.y ? x1 : x0;
    unsigned short* p0 = blockIdx.y ? b0 : a0;
    unsigned short* p1 = blockIdx.y ? b1 : a1;
    unsigned short s0, s1;
    split1h(x[i], s0, s1);
    p0[i] = s0; p1[i] = s1;
}

// ---------------- init p = SOS --------------------------------------------
__global__ void initp_kernel() {
    int i = blockIdx.x * blockDim.x + threadIdx.x;
    if (i < BB) g_p[i] = SOS;
}

// ---------------- T0[a][n] = b_ih0[n] + sum_k emb[a][k] * w_ih0[n][k] ------
__global__ void table_kernel(const float* __restrict__ emb,
                             const float* __restrict__ w_ih0,
                             const float* __restrict__ b_ih0) {
    int n = blockIdx.x * blockDim.x + threadIdx.x;
    int a = blockIdx.y;
    if (n >= H3) return;
    float acc = b_ih0[n];
    const float* er = emb + a * EMBQ;
    const float* wr = w_ih0 + n * EMBQ;
#pragma unroll
    for (int k = 0; k < EMBQ; k++) acc += er[k] * wr[k];
    g_T0[a * H3 + n] = acc;
}

// ---------------- fp32 SIMT GEMM (init only): tanh + split to h0/h1 -------
#define BMT 128
#define BNT 128
#define BKT 16

__device__ __forceinline__ unsigned long long splat2(float a) {
    unsigned long long d;
    unsigned int u = __float_as_uint(a);
    asm("mov.b64 %0, {%1, %1};" : "=l"(d) : "r"(u));
    return d;
}
__device__ __forceinline__ void fma2(unsigned long long& c, unsigned long long a, unsigned long long b) {
    asm("fma.rn.f32x2 %0, %1, %2, %0;" : "+l"(c) : "l"(a), "l"(b));
}
__device__ __forceinline__ float2 unpack2(unsigned long long c) {
    unsigned int lo, hi;
    asm("mov.b64 {%0, %1}, %2;" : "=r"(lo), "=r"(hi) : "l"(c));
    float2 f; f.x = __uint_as_float(lo); f.y = __uint_as_float(hi);
    return f;
}

__global__ __launch_bounds__(256, 2) void gemm_init_kernel(
    const float* __restrict__ A, const float* __restrict__ W,
    const float* __restrict__ bias, int K)
{
    __shared__ float As[BKT][BMT];
    __shared__ float Ws[BKT][BNT];

    int tid = threadIdx.x;
    int m0 = blockIdx.y * BMT;
    int n0 = blockIdx.x * BNT;
    int tr = tid >> 4;
    int tc = tid & 15;

    unsigned long long acc[8][4];
#pragma unroll
    for (int i = 0; i < 8; i++)
#pragma unroll
        for (int j = 0; j < 4; j++) acc[i][j] = 0ull;

    for (int kt = 0; kt < K; kt += BKT) {
#pragma unroll
        for (int l = 0; l < 2; l++) {
            int fid = tid + l * 256;
            int r = fid >> 2;
            int c4 = (fid & 3) * 4;
            float4 va = *(const float4*)(A + (size_t)(m0 + r) * K + kt + c4);
            As[c4 + 0][r] = va.x; As[c4 + 1][r] = va.y;
            As[c4 + 2][r] = va.z; As[c4 + 3][r] = va.w;
            float4 vw = *(const float4*)(W + (size_t)(n0 + r) * K + kt + c4);
            Ws[c4 + 0][r] = vw.x; Ws[c4 + 1][r] = vw.y;
            Ws[c4 + 2][r] = vw.z; Ws[c4 + 3][r] = vw.w;
        }
        __syncthreads();
#pragma unroll
        for (int k = 0; k < BKT; k++) {
            float4 a0 = *(const float4*)&As[k][tr * 8];
            float4 a1 = *(const float4*)&As[k][tr * 8 + 4];
            float av[8] = {a0.x, a0.y, a0.z, a0.w, a1.x, a1.y, a1.z, a1.w};
            const unsigned long long* wp = (const unsigned long long*)&Ws[k][0];
            unsigned long long bv[4];
#pragma unroll
            for (int j = 0; j < 4; j++) bv[j] = wp[tc * 4 + j];
#pragma unroll
            for (int i = 0; i < 8; i++) {
                unsigned long long as = splat2(av[i]);
#pragma unroll
                for (int j = 0; j < 4; j++) fma2(acc[i][j], as, bv[j]);
            }
        }
        __syncthreads();
    }

    int nb = n0 + tc * 8;
    float bb[8];
#pragma unroll
    for (int j = 0; j < 8; j++) bb[j] = bias[nb + j];

#pragma unroll
    for (int i = 0; i < 8; i++) {
        int m = m0 + tr * 8 + i;
#pragma unroll
        for (int jp = 0; jp < 4; jp++) {
            float2 f = unpack2(acc[i][jp]);
            float v0 = tanhf(f.x + bb[2 * jp]);
            float v1 = tanhf(f.y + bb[2 * jp + 1]);
            int n = nb + 2 * jp;
            if (n < HID) {
                g_h0[m * HID + n] = v0;
                g_h0[m * HID + n + 1] = v1;
            } else {
                g_h1[m * HID + n - HID] = v0;
                g_h1[m * HID + n - HID + 1] = v1;
            }
        }
    }
}

// ---------------- mma.sync fp16x3 GEMM: C = bias + A*W^T (fp32-emulated) ---
// 256 threads, 8 warps in 2x4 grid, warp tile 64x32; CTA tile 128x128.
// Main product a0*b0 -> fp32 acc; corrections a0*b1s + a1s*b0 -> fp16 acc.
// C = acc0 + acc1/2048 + bias.
#define KCH 64
#define NCHUNK (HID / KCH)       // 8
#define PART_BYTES (128 * 128)   // 128 rows x 128B (one limb, one chunk)
#define BUF_BYTES (4 * PART_BYTES)   // A0,A1,B0,B1
#define NSTAGE 3
#define NT 256

__global__ __launch_bounds__(NT, 1) void gemm_mma_kernel(
    const unsigned short* __restrict__ A, const unsigned short* __restrict__ W,
    const float* __restrict__ bias, float* __restrict__ C,
    int hplane, int wplane)
{
    extern __shared__ __align__(1024) char smem[];
    const uint32_t sb = smem_u32(smem);
    const int tid = threadIdx.x;
    const int wid = tid >> 5;
    const int lane = tid & 31;
    const int n0 = blockIdx.x * 128;
    const int m0 = blockIdx.y * 128;

    const int wm = wid & 1;          // 2 warp-rows (64 m each)
    const int wn = wid >> 1;         // 4 warp-cols (32 n each)
    const int mW = wm * 64;
    const int nW = wn * 32;

    // ldmatrix per-thread address components
    const int a_row = ((lane >> 3) & 1) * 8 + (lane & 7);
    const int a_hb  = (lane >> 4) * 16;          // k-half byte for A
    const int b_row = ((lane >> 4) & 1) * 8 + (lane & 7);
    const int b_hb  = ((lane >> 3) & 1) * 16;    // k-half byte for B

    const char* Ap[2];
    const char* Bp[2];
#pragma unroll
    for (int p = 0; p < 2; p++) {
        Ap[p] = (const char*)(A + (size_t)p * hplane);
        Bp[p] = (const char*)(W + (size_t)p * wplane);
    }

    float    c0[4][4][4];        // fp32 main accumulators
    uint32_t c1[4][4][2];        // fp16x2 correction accumulators
#pragma unroll
    for (int i = 0; i < 4; i++)
#pragma unroll
        for (int j = 0; j < 4; j++) {
#pragma unroll
            for (int q = 0; q < 4; q++) c0[i][j][q] = 0.f;
            c1[i][j][0] = 0u; c1[i][j][1] = 0u;
        }

    auto load_chunk = [&](int c) {
        int buf = c % NSTAGE;
        uint32_t base = sb + buf * BUF_BYTES;
#pragma unroll
        for (int p = 0; p < 2; p++) {
            const char* srcA = Ap[p] + (size_t)m0 * 1024 + c * 128;   // row stride 512*2B
            uint32_t da = base + p * PART_BYTES;
#pragma unroll
            for (int i = tid; i < 1024; i += NT) {
                int row = i >> 3, seg = (i & 7) << 4;
                cp16(da + SWZ(row * 128 + seg), srcA + (size_t)row * 1024 + seg);
            }
            const char* srcB = Bp[p] + (size_t)n0 * 1024 + c * 128;
            uint32_t db = base + (2 + p) * PART_BYTES;
#pragma unroll
            for (int i = tid; i < 1024; i += NT) {
                int row = i >> 3, seg = (i & 7) << 4;
                cp16(db + SWZ(row * 128 + seg), srcB + (size_t)row * 1024 + seg);
            }
        }
        asm volatile("cp.async.commit_group;" ::: "memory");
    };

    load_chunk(0);
    load_chunk(1);

    for (int c = 0; c < NCHUNK; c++) {
        if (c + 1 < NCHUNK) {
            asm volatile("cp.async.wait_group 1;" ::: "memory");   // chunk c arrived
        } else {
            asm volatile("cp.async.wait_group 0;" ::: "memory");
        }
        __syncthreads();   // all warps finished consuming chunk c-1; chunk c visible
        if (c + 2 < NCHUNK) load_chunk(c + 2);

        uint32_t base = sb + (c % NSTAGE) * BUF_BYTES;

#pragma unroll
        for (int kk = 0; kk < 4; kk++) {
            const int k0b = kk * 32;
            uint32_t a0f[4][4], a1f[4][4], b0f[8], b1f[8];

            auto ldA = [&](int p, uint32_t (*af)[4]) {
                uint32_t pb = base + p * PART_BYTES;
#pragma unroll
                for (int mi = 0; mi < 4; mi++) {
                    int row = mW + mi * 16 + a_row;
                    ldsm4(af[mi], pb + SWZ(row * 128 + k0b + a_hb));
                }
            };
            auto ldB = [&](int p, uint32_t* bf) {
                uint32_t pb = base + (2 + p) * PART_BYTES;
#pragma unroll
                for (int j = 0; j < 2; j++) {
                    int row = nW + j * 16 + b_row;
                    ldsm4(bf + j * 4, pb + SWZ(row * 128 + k0b + b_hb));
                }
            };

            ldA(0, a0f); ldB(0, b0f);
            // main product: fp32 accumulate
#pragma unroll
            for (int mi = 0; mi < 4; mi++)
#pragma unroll
                for (int ni = 0; ni < 4; ni++)
                    mma16816h(c0[mi][ni], a0f[mi], b0f + ni * 2);
            // corrections: fp16 accumulate
            ldB(1, b1f);
#pragma unroll
            for (int mi = 0; mi < 4; mi++)
#pragma unroll
                for (int ni = 0; ni < 4; ni++)
                    mma16816hh(c1[mi][ni], a0f[mi], b1f + ni * 2);
            ldA(1, a1f);
#pragma unroll
            for (int mi = 0; mi < 4; mi++)
#pragma unroll
                for (int ni = 0; ni < 4; ni++)
                    mma16816hh(c1[mi][ni], a1f[mi], b0f + ni * 2);
        }
    }

    // ---- epilogue: combine limbs + bias, direct stores ----
    const int tr = lane >> 2;
    const int tc2 = (lane & 3) * 2;
#pragma unroll
    for (int mi = 0; mi < 4; mi++) {
        int row = m0 + mW + mi * 16 + tr;
#pragma unroll
        for (int ni = 0; ni < 4; ni++) {
            int col = n0 + nW + ni * 8 + tc2;
            float bx = bias[col], by = bias[col + 1];
            float2 e0 = __half22float2(*reinterpret_cast<__half2*>(&c1[mi][ni][0]));
            float2 e1 = __half22float2(*reinterpret_cast<__half2*>(&c1[mi][ni][1]));
            float2 v0;
            v0.x = c0[mi][ni][0] + e0.x * INV_LIMB + bx;
            v0.y = c0[mi][ni][1] + e0.y * INV_LIMB + by;
            *(float2*)&C[(size_t)row * H3 + col] = v0;
            float2 v1;
            v1.x = c0[mi][ni][2] + e1.x * INV_LIMB + bx;
            v1.y = c0[mi][ni][3] + e1.y * INV_LIMB + by;
            *(float2*)&C[(size_t)(row + 8) * H3 + col] = v1;
        }
    }
}

// ---------------- gate0 (gi from table, gh in G1; emit h0 + limbs) --------
__global__ __launch_bounds__(256) void gate0_kernel() {
    int idx = blockIdx.x * blockDim.x + threadIdx.x;
    int b = idx >> 7;
    int q = (idx & 127) << 2;
    int p = g_p[b];
    const float* T = g_T0 + p * H3;
    float4 Tr = *(const float4*)(T + q);
    float4 Tz = *(const float4*)(T + HID + q);
    float4 Tn = *(const float4*)(T + 2 * HID + q);
    const float* Gb = g_G1 + (size_t)b * H3;
    float4 Gr = *(const float4*)(Gb + q);
    float4 Gz = *(const float4*)(Gb + HID + q);
    float4 Gn = *(const float4*)(Gb + 2 * HID + q);
    float4 h = *(const float4*)(g_h0 + b * HID + q);
    float4 o;
    o.x = gru_elem(Tr.x, Tz.x, Tn.x, Gr.x, Gz.x, Gn.x, h.x);
    o.y = gru_elem(Tr.y, Tz.y, Tn.y, Gr.y, Gz.y, Gn.y, h.y);
    o.z = gru_elem(Tr.z, Tz.z, Tn.z, Gr.z, Gz.z, Gn.z, h.z);
    o.w = gru_elem(Tr.w, Tz.w, Tn.w, Gr.w, Gz.w, Gn.w, h.w);
    size_t off = (size_t)b * HID + q;
    *(float4*)(g_h0 + off) = o;
    split_store4h(o, off, g_h0p[0], g_h0p[1]);
}

// ---------------- fused gate1 + output (reads G3/G2) ----------------------
__global__ __launch_bounds__(256) void gate1out_kernel(const float* __restrict__ w_out,
                                                       const float* __restrict__ b_out,
                                                       float* __restrict__ Y, int s) {
    __shared__ float hs[8][HID];
    int tid = threadIdx.x;
    int wr = tid >> 5;
    int lane = tid & 31;
    int b0 = blockIdx.x * 8;
    int b = b0 + wr;

    // ---- phase 1: gate (each thread: 16 cols of its row) ----
    const float* Gi = g_G3 + (size_t)b * H3;
    const float* Gh = g_G2 + (size_t)b * H3;
    int q0 = lane * 16;
#pragma unroll
    for (int j = 0; j < 4; j++) {
        int q = q0 + j * 4;
        float4 Ir = *(const float4*)(Gi + q);
        float4 Iz = *(const float4*)(Gi + HID + q);
        float4 In = *(const float4*)(Gi + 2 * HID + q);
        float4 Hr = *(const float4*)(Gh + q);
        float4 Hz = *(const float4*)(Gh + HID + q);
        float4 Hn = *(const float4*)(Gh + 2 * HID + q);
        float4 h = *(const float4*)(g_h1 + (size_t)b * HID + q);
        float4 o;
        o.x = gru_elem(Ir.x, Iz.x, In.x, Hr.x, Hz.x, Hn.x, h.x);
        o.y = gru_elem(Ir.y, Iz.y, In.y, Hr.y, Hz.y, Hn.y, h.y);
        o.z = gru_elem(Ir.z, Iz.z, In.z, Hr.z, Hz.z, Hn.z, h.z);
        o.w = gru_elem(Ir.w, Iz.w, In.w, Hr.w, Hz.w, Hn.w, h.w);
        size_t off = (size_t)b * HID + q;
        *(float4*)(g_h1 + off) = o;
        split_store4h(o, off, g_h1p[0], g_h1p[1]);
        *(float4*)&hs[wr][q] = o;
    }
    __syncthreads();

    // ---- phase 2: logits + log_softmax + argmax ----
    int na = lane, nb = lane + 32;
    const float4* w0p = (const float4*)(w_out + na * HID);
    const float4* w1p = (const float4*)(w_out + nb * HID);
    const float4* hp = (const float4*)&hs[wr][0];
    float acc0 = 0.f, acc1 = 0.f;
#pragma unroll 8
    for (int k = 0; k < HID / 4; k++) {
        float4 hv = hp[k];
        float4 w0 = w0p[k];
        acc0 += hv.x * w0.x + hv.y * w0.y + hv.z * w0.z + hv.w * w0.w;
        float4 w1 = w1p[k];
        acc1 += hv.x * w1.x + hv.y * w1.y + hv.z * w1.z + hv.w * w1.w;
    }
    float l0 = acc0 + b_out[na];
    float l1 = acc1 + b_out[nb];

    float mx = fmaxf(l0, l1);
#pragma unroll
    for (int off = 16; off; off >>= 1) mx = fmaxf(mx, __shfl_xor_sync(0xffffffffu, mx, off));
    float se = expf(l0 - mx) + expf(l1 - mx);
#pragma unroll
    for (int off = 16; off; off >>= 1) se += __shfl_xor_sync(0xffffffffu, se, off);
    float lse = logf(se);

    float* yr = Y + ((size_t)s * BB + b) * ATOM;
    yr[na] = l0 - mx - lse;
    yr[nb] = l1 - mx - lse;

    float v; int ix;
    if (l0 >= l1) { v = l0; ix = na; } else { v = l1; ix = nb; }
#pragma unroll
    for (int off = 16; off; off >>= 1) {
        float ov = __shfl_xor_sync(0xffffffffu, v, off);
        int oi = __shfl_xor_sync(0xffffffffu, ix, off);
        if (ov > v || (ov == v && oi < ix)) { v = ov; ix = oi; }
    }
    if (lane == 0) g_p[b] = ix;
}

// ---------------- launch ---------------------------------------------------
extern "C" void kernel_launch(void* const* d_in, const int* in_sizes, int n_in,
                              void* d_out, int out_size) {
    const float* enc   = (const float*)d_in[0];
    const float* emb   = (const float*)d_in[1];
    const float* w_h0  = (const float*)d_in[2];
    const float* b_h0  = (const float*)d_in[3];
    const float* w_ih0 = (const float*)d_in[4];
    const float* w_hh0 = (const float*)d_in[5];
    const float* b_ih0 = (const float*)d_in[6];
    const float* b_hh0 = (const float*)d_in[7];
    const float* w_ih1 = (const float*)d_in[8];
    const float* w_hh1 = (const float*)d_in[9];
    const float* b_ih1 = (const float*)d_in[10];
    const float* b_hh1 = (const float*)d_in[11];
    const float* w_out = (const float*)d_in[12];
    const float* b_out = (const float*)d_in[13];
    float* Y = (float*)d_out;

    float *h0p, *h1p, *G1p, *G2p, *G3p;
    unsigned short *h0l, *h1l, *w0l, *w1l, *w2l;
    cudaGetSymbolAddress((void**)&h0p, g_h0);
    cudaGetSymbolAddress((void**)&h1p, g_h1);
    cudaGetSymbolAddress((void**)&G1p, g_G1);
    cudaGetSymbolAddress((void**)&G2p, g_G2);
    cudaGetSymbolAddress((void**)&G3p, g_G3);
    cudaGetSymbolAddress((void**)&h0l, g_h0p);
    cudaGetSymbolAddress((void**)&h1l, g_h1p);
    cudaGetSymbolAddress((void**)&w0l, g_w0p);
    cudaGetSymbolAddress((void**)&w1l, g_w1p);
    cudaGetSymbolAddress((void**)&w2l, g_w2p);

    const int HN = BB * HID;       // h limb plane size
    const int WN = H3 * HID;       // weight limb plane size

    const int smem_sz = NSTAGE * BUF_BYTES;   // 3 * 65536 = 196608
    cudaFuncSetAttribute(gemm_mma_kernel, cudaFuncAttributeMaxDynamicSharedMemorySize, smem_sz);

    // one-time stream/event setup (host resources only; no device memory)
    static cudaStream_t sE = nullptr;
    static cudaEvent_t evGh0 = nullptr, evG0 = nullptr, evGi1 = nullptr, evG1o = nullptr;
    if (sE == nullptr) {
        cudaStreamCreateWithFlags(&sE, cudaStreamNonBlocking);
        cudaEventCreateWithFlags(&evGh0, cudaEventDisableTiming);
        cudaEventCreateWithFlags(&evG0,  cudaEventDisableTiming);
        cudaEventCreateWithFlags(&evGi1, cudaEventDisableTiming);
        cudaEventCreateWithFlags(&evG1o, cudaEventDisableTiming);
    }

    // ---- init (ordered so launch L6 = first gemm_mma, for ncu capture) ----
    // L0: h_init = tanh(enc @ w_h0.T + b_h0) -> g_h0 / g_h1
    gemm_init_kernel<<<dim3((2 * HID) / BNT, BB / BMT), 256>>>(enc, w_h0, b_h0, ENC);
    // L1: split h0, h1 into fp16 limbs (merged)
    split2_dual_kernel<<<dim3((HN + 255) / 256, 2), 256>>>(
        h0p, h0l, h0l + HN, h1p, h1l, h1l + HN, HN);
    // L2: split w_hh0 and w_hh1 (merged)
    split2_dual_kernel<<<dim3((WN + 255) / 256, 2), 256>>>(
        w_hh0, w0l, w0l + WN, w_hh1, w2l, w2l + WN, WN);
    // L3: T0 table
    table_kernel<<<dim3(H3 / 256, ATOM), 256>>>(emb, w_ih0, b_ih0);
    // L4: p = SOS
    initp_kernel<<<BB / 256, 256>>>();
    // L5: split w_ih1
    split2_dual_kernel<<<dim3((WN + 255) / 256, 1), 256>>>(
        w_ih1, w1l, w1l + WN, w_ih1, w1l, w1l + WN, WN);

    // seed events so first-iteration waits are valid
    cudaEventRecord(evG0, 0);
    cudaEventRecord(evG1o, 0);

    dim3 ggrid(H3 / 128, BB / 128);           // 12 x 64
    int gate_blocks = BB * (HID / 4) / 256;   // 4096

    for (int s = 0; s < STEPS; s++) {
        // G-stream (default): gh0 = h0 @ w_hh0.T + b_hh0 -> G1   (needs gate0(s-1))
        cudaStreamWaitEvent(0, evG0, 0);
        gemm_mma_kernel<<<ggrid, NT, smem_sz>>>(h0l, w0l, b_hh0, G1p, HN, WN);   // L6 @ s=0
        cudaEventRecord(evGh0, 0);
        // G-stream: gh1 = h1_old @ w_hh1.T + b_hh1 -> G2         (needs gate1out(s-1))
        cudaStreamWaitEvent(0, evG1o, 0);
        gemm_mma_kernel<<<ggrid, NT, smem_sz>>>(h1l, w2l, b_hh1, G2p, HN, WN);
        // E-stream: gate0 (overlaps gh1)
        cudaStreamWaitEvent(sE, evGh0, 0);
        gate0_kernel<<<gate_blocks, 256, 0, sE>>>();
        cudaEventRecord(evG0, sE);
        // G-stream: gi1 = h0_new @ w_ih1.T + b_ih1 -> G3         (needs gate0(s))
        cudaStreamWaitEvent(0, evG0, 0);
        gemm_mma_kernel<<<ggrid, NT, smem_sz>>>(h0l, w1l, b_ih1, G3p, HN, WN);
        cudaEventRecord(evGi1, 0);
        // E-stream: gate1out (reads G3/G2; overlaps gh0 of next step)
        cudaStreamWaitEvent(sE, evGi1, 0);
        gate1out_kernel<<<BB / 8, 256, 0, sE>>>(w_out, b_out, Y, s);
        cudaEventRecord(evG1o, sE);
    }
    // join E back into origin stream before returning
    cudaStreamWaitEvent(0, evG1o, 0);
}